// round 6
// baseline (speedup 1.0000x reference)
#include <cuda_runtime.h>
#include <cuda_bf16.h>

#define VSZ 32000
#define HSZ 256
#define BSZ 256
#define SSZ 512

typedef unsigned long long ull;

// Scratch (device globals; no allocation allowed)
__device__ float g_eproj[(size_t)VSZ * 768];   // emb @ [Wz;Wr;Wh]^T + biases
__device__ float g_hlast[BSZ * HSZ];
// Row-major packed bf16 U (NO transpose):
//  g_uzrr[j][kp] = { bf16x2(Uz[j][2kp],Uz[j][2kp+1]), bf16x2(Ur[j][2kp],Ur[j][2kp+1]) }
//  g_uhh [j][kp] =   bf16x2(Uh[j][2kp],Uh[j][2kp+1])
__device__ uint2    g_uzrr[256 * 128];
__device__ unsigned g_uhh[256 * 128];

// ---- packed f32x2 helpers (Blackwell sm_103a) ----
__device__ __forceinline__ ull pk2(float lo, float hi) {
    ull r;
    asm("mov.b64 %0, {%1, %2};" : "=l"(r) : "f"(lo), "f"(hi));
    return r;
}
__device__ __forceinline__ void fma2(ull& d, ull a, ull b) {
    asm("fma.rn.f32x2 %0, %1, %2, %0;" : "+l"(d) : "l"(a), "l"(b));
}
__device__ __forceinline__ float hsum2(ull v) {
    float lo, hi;
    asm("mov.b64 {%0, %1}, %2;" : "=f"(lo), "=f"(hi) : "l"(v));
    return lo + hi;
}
// bf16x2 (lo16, hi16) -> f32x2 pair, exact
__device__ __forceinline__ ull bf2f2(unsigned v) {
    ull r;
    asm("{\n\t.reg .b32 lo, hi;\n\t"
        "shl.b32 lo, %1, 16;\n\t"
        "and.b32 hi, %1, 0xFFFF0000;\n\t"
        "mov.b64 %0, {lo, hi};\n\t}" : "=l"(r) : "r"(v));
    return r;
}
__device__ __forceinline__ float fast_sigm(float x) {
    float e, r;
    asm("ex2.approx.ftz.f32 %0, %1;" : "=f"(e) : "f"(-1.4426950408889634f * x));
    asm("rcp.approx.ftz.f32 %0, %1;" : "=f"(r) : "f"(1.0f + e));
    return r;
}
__device__ __forceinline__ float fast_tanh(float x) {
    float r;
    asm("tanh.approx.f32 %0, %1;" : "=f"(r) : "f"(x));
    return r;
}
__device__ __forceinline__ unsigned pkbf(float lo, float hi) {
    unsigned short l = __bfloat16_as_ushort(__float2bfloat16(lo));
    unsigned short h = __bfloat16_as_ushort(__float2bfloat16(hi));
    return ((unsigned)h << 16) | (unsigned)l;
}

// ============================================================================
// Pack U (row-major, k-pair packed bf16)
// ============================================================================
__global__ void pack_u(const float* __restrict__ Uz, const float* __restrict__ Ur,
                       const float* __restrict__ Uh)
{
    const int j  = blockIdx.x;     // 0..255 (output row)
    const int kp = threadIdx.x;    // 0..127 (k pair)
    const int k0 = 2 * kp;
    g_uzrr[j * 128 + kp] = make_uint2(
        pkbf(Uz[j * 256 + k0], Uz[j * 256 + k0 + 1]),
        pkbf(Ur[j * 256 + k0], Ur[j * 256 + k0 + 1]));
    g_uhh[j * 128 + kp] = pkbf(Uh[j * 256 + k0], Uh[j * 256 + k0 + 1]);
}

// Tiny init kernel; also shifts the scan to ncu capture slot (-s 5).
__global__ void init_hlast()
{
    g_hlast[blockIdx.x * 256 + threadIdx.x] = 0.0f;
}

// ============================================================================
// SGEMM-NT with bias (~90% of scalar f32x2 floor)
// ============================================================================
__global__ void __launch_bounds__(256) sgemm_nt_bias(
    const float* __restrict__ A, const float* __restrict__ Bw,
    const float* __restrict__ bias1, const float* __restrict__ bias2,
    float* __restrict__ C, int ldc, int coloff)
{
    __shared__ __align__(16) float As[16][132];
    __shared__ __align__(16) float Bs[16][132];
    const int t  = threadIdx.x;
    const int tm = t >> 4;
    const int tn = t & 15;

    ull acc[8][4];
#pragma unroll
    for (int i = 0; i < 8; i++)
#pragma unroll
        for (int j = 0; j < 4; j++) acc[i][j] = 0ULL;

    const float* Ab = A  + (size_t)blockIdx.x * 128 * 256;
    const float* Bb = Bw + (size_t)blockIdx.y * 128 * 256;
    const int lr = t >> 2;
    const int lk = (t & 3) << 2;

    for (int k0 = 0; k0 < 256; k0 += 16) {
        float4 a0 = *(const float4*)(Ab + (size_t)lr * 256 + k0 + lk);
        float4 a1 = *(const float4*)(Ab + (size_t)(lr + 64) * 256 + k0 + lk);
        float4 b0 = *(const float4*)(Bb + (size_t)lr * 256 + k0 + lk);
        float4 b1 = *(const float4*)(Bb + (size_t)(lr + 64) * 256 + k0 + lk);
        __syncthreads();
        As[lk + 0][lr] = a0.x; As[lk + 1][lr] = a0.y;
        As[lk + 2][lr] = a0.z; As[lk + 3][lr] = a0.w;
        As[lk + 0][lr + 64] = a1.x; As[lk + 1][lr + 64] = a1.y;
        As[lk + 2][lr + 64] = a1.z; As[lk + 3][lr + 64] = a1.w;
        Bs[lk + 0][lr] = b0.x; Bs[lk + 1][lr] = b0.y;
        Bs[lk + 2][lr] = b0.z; Bs[lk + 3][lr] = b0.w;
        Bs[lk + 0][lr + 64] = b1.x; Bs[lk + 1][lr + 64] = b1.y;
        Bs[lk + 2][lr + 64] = b1.z; Bs[lk + 3][lr + 64] = b1.w;
        __syncthreads();
#pragma unroll
        for (int kk = 0; kk < 16; kk++) {
            float4 av0 = *(const float4*)(&As[kk][tm * 8]);
            float4 av1 = *(const float4*)(&As[kk][tm * 8 + 4]);
            const ull* bp = (const ull*)(&Bs[kk][tn * 8]);
            ull b2_0 = bp[0], b2_1 = bp[1], b2_2 = bp[2], b2_3 = bp[3];
            float av[8] = {av0.x, av0.y, av0.z, av0.w, av1.x, av1.y, av1.z, av1.w};
#pragma unroll
            for (int i = 0; i < 8; i++) {
                ull a2 = pk2(av[i], av[i]);
                fma2(acc[i][0], a2, b2_0);
                fma2(acc[i][1], a2, b2_1);
                fma2(acc[i][2], a2, b2_2);
                fma2(acc[i][3], a2, b2_3);
            }
        }
    }

    const int row0 = blockIdx.x * 128 + tm * 8;
    const int col0 = blockIdx.y * 128 + tn * 8;
#pragma unroll
    for (int i = 0; i < 8; i++) {
#pragma unroll
        for (int j = 0; j < 4; j++) {
            float lo, hi;
            asm("mov.b64 {%0, %1}, %2;" : "=f"(lo), "=f"(hi) : "l"(acc[i][j]));
            int n0 = col0 + j * 2;
            float e0 = bias1[n0]     + (bias2 ? bias2[n0]     : 0.0f);
            float e1 = bias1[n0 + 1] + (bias2 ? bias2[n0 + 1] : 0.0f);
            C[(size_t)(row0 + i) * ldc + coloff + n0]     = lo + e0;
            C[(size_t)(row0 + i) * ldc + coloff + n0 + 1] = hi + e1;
        }
    }
}

// ============================================================================
// GRU scan v6: 128 CTAs x 2 batch rows x 256 threads.
// Thread = one hidden column, BOTH batch rows, FULL 256-k dot per gate.
// -> zero cross-thread reduction; 2 barriers/step; no red smem.
// U streams row-major per thread; k<128 of zr and uh pinned in SMEM (196KB);
// k>=128 streamed from global through depth-16 register rings with
// cross-step wraparound. h and r*h stored as (h0,h0',h1,h1') float4 so one
// broadcast LDS.128 per k-pair feeds 4 fma2 directly.
// ============================================================================
#define SCAN_SM_BYTES 200704

__global__ void __launch_bounds__(256, 1) gru_scan6(const int* __restrict__ x)
{
    extern __shared__ __align__(16) char smraw[];
    uint2*    pin_zr = (uint2*)smraw;                  // [col][kp<64]  131072 B
    unsigned* pin_uh = (unsigned*)(smraw + 131072);    // [col][kp<64]   65536 B
    float4*   hbufP  = (float4*)(smraw + 196608);      // [kp]: h0,h0',h1,h1'
    float4*   srhP   = (float4*)(smraw + 198656);      // [kp]: rh0,rh0',rh1,rh1'

    const int t  = threadIdx.x;        // hidden column 0..255
    const int b0 = blockIdx.x * 2;

    // ---- pin k<128 halves + zero state ----
    for (int i = t; i < 16384; i += 256)
        pin_zr[i] = g_uzrr[((i >> 6) * 128) + (i & 63)];
    for (int i = t; i < 16384; i += 256)
        pin_uh[i] = g_uhh[((i >> 6) * 128) + (i & 63)];
    if (t < 128) {
        hbufP[t] = make_float4(0.f, 0.f, 0.f, 0.f);
        srhP[t]  = make_float4(0.f, 0.f, 0.f, 0.f);
    }
    __syncthreads();

    const uint2*    zs = pin_zr + t * 64;     // smem: kp 0..63
    const uint2*    zg = g_uzrr + t * 128;    // global: kp 64..127
    const unsigned* hs = pin_uh + t * 64;
    const unsigned* hg = g_uhh  + t * 128;

    // depth-16 global rings (persist across steps; cross-step wraparound)
    uint2 zr_r[16];
    unsigned uh_r[16];
#pragma unroll
    for (int i = 0; i < 16; i++) {
        zr_r[i] = zg[64 + i];
        uh_r[i] = hg[64 + i];
    }

    float hold0 = 0.0f, hold1 = 0.0f;

    // e/token pipeline (1 step ahead for e, 2 for tokens)
    int tokA = __ldg(&x[b0 * SSZ]);
    int tokB = __ldg(&x[(b0 + 1) * SSZ]);
    const float* eA = g_eproj + (size_t)tokA * 768;
    const float* eB = g_eproj + (size_t)tokB * 768;
    float ez0 = __ldg(eA + t),       ez1 = __ldg(eB + t);
    float er0 = __ldg(eA + 256 + t), er1 = __ldg(eB + 256 + t);
    float eh0 = __ldg(eA + 512 + t), eh1 = __ldg(eB + 512 + t);
    int tokA1 = __ldg(&x[b0 * SSZ + 1]);
    int tokB1 = __ldg(&x[(b0 + 1) * SSZ + 1]);

    for (int s = 0; s < SSZ; s++) {
        // ================= phase 1: z, r full dots =================
        ull az0 = 0, az1 = 0, ar0 = 0, ar1 = 0;
#pragma unroll
        for (int kp = 0; kp < 64; kp++) {              // smem half
            uint2 u = zs[kp];
            ull uz2 = bf2f2(u.x);
            ull ur2 = bf2f2(u.y);
            ulonglong2 hp = *(const ulonglong2*)(hbufP + kp);
            fma2(az0, uz2, hp.x); fma2(az1, uz2, hp.y);
            fma2(ar0, ur2, hp.x); fma2(ar1, ur2, hp.y);
        }
#pragma unroll
        for (int i = 0; i < 64; i++) {                 // global half (ring)
            uint2 u = zr_r[i & 15];
            zr_r[i & 15] = zg[64 + ((i + 16) & 63)];
            ull uz2 = bf2f2(u.x);
            ull ur2 = bf2f2(u.y);
            ulonglong2 hp = *(const ulonglong2*)(hbufP + 64 + i);
            fma2(az0, uz2, hp.x); fma2(az1, uz2, hp.y);
            fma2(ar0, ur2, hp.x); fma2(ar1, ur2, hp.y);
        }

        // gates (no reduction needed)
        float z0 = fast_sigm(hsum2(az0) + ez0);
        float z1 = fast_sigm(hsum2(az1) + ez1);
        float r0 = fast_sigm(hsum2(ar0) + er0);
        float r1 = fast_sigm(hsum2(ar1) + er1);
        {
            float* sp = (float*)(srhP + (t >> 1)) + (t & 1);
            sp[0] = r0 * hold0;      // lane (t&1) of (rh0, rh0')
            sp[2] = r1 * hold1;      // lane (t&1) of (rh1, rh1')
        }
        // prefetch next step's z/r e-values
        const float* enA = g_eproj + (size_t)tokA1 * 768;
        const float* enB = g_eproj + (size_t)tokB1 * 768;
        ez0 = __ldg(enA + t);       ez1 = __ldg(enB + t);
        er0 = __ldg(enA + 256 + t); er1 = __ldg(enB + 256 + t);
        __syncthreads();

        // ================= phase 2: h_tilde full dot =================
        ull ah0 = 0, ah1 = 0;
#pragma unroll
        for (int kp = 0; kp < 64; kp++) {              // smem half
            ull uh2 = bf2f2(hs[kp]);
            ulonglong2 sp2 = *(const ulonglong2*)(srhP + kp);
            fma2(ah0, uh2, sp2.x); fma2(ah1, uh2, sp2.y);
        }
#pragma unroll
        for (int i = 0; i < 64; i++) {                 // global half (ring)
            unsigned v = uh_r[i & 15];
            uh_r[i & 15] = hg[64 + ((i + 16) & 63)];
            ull uh2 = bf2f2(v);
            ulonglong2 sp2 = *(const ulonglong2*)(srhP + 64 + i);
            fma2(ah0, uh2, sp2.x); fma2(ah1, uh2, sp2.y);
        }

        float ht0 = fast_tanh(hsum2(ah0) + eh0);
        float ht1 = fast_tanh(hsum2(ah1) + eh1);
        hold0 += z0 * (ht0 - hold0);
        hold1 += z1 * (ht1 - hold1);
        {
            float* hp = (float*)(hbufP + (t >> 1)) + (t & 1);
            hp[0] = hold0;
            hp[2] = hold1;
        }
        // prefetch next step's h e-values; advance token pipeline to s+2
        eh0 = __ldg(enA + 512 + t);
        eh1 = __ldg(enB + 512 + t);
        {
            int s2 = (s + 2 < SSZ) ? s + 2 : SSZ - 1;
            tokA1 = __ldg(&x[b0 * SSZ + s2]);
            tokB1 = __ldg(&x[(b0 + 1) * SSZ + s2]);
        }
        __syncthreads();
    }

    g_hlast[(size_t)b0 * HSZ + t]       = hold0;
    g_hlast[(size_t)(b0 + 1) * HSZ + t] = hold1;
}

// ============================================================================
extern "C" void kernel_launch(void* const* d_in, const int* in_sizes, int n_in,
                              void* d_out, int out_size)
{
    const int*   x   = (const int*)  d_in[0];
    const float* emb = (const float*)d_in[1];
    const float* Wz  = (const float*)d_in[2];
    const float* bz  = (const float*)d_in[3];
    const float* Uz  = (const float*)d_in[4];
    const float* buz = (const float*)d_in[5];
    const float* Wr  = (const float*)d_in[6];
    const float* br  = (const float*)d_in[7];
    const float* Ur  = (const float*)d_in[8];
    const float* bur = (const float*)d_in[9];
    const float* Wh  = (const float*)d_in[10];
    const float* bh  = (const float*)d_in[11];
    const float* Uh  = (const float*)d_in[12];
    const float* buh = (const float*)d_in[13];
    const float* Wf  = (const float*)d_in[14];
    const float* bf  = (const float*)d_in[15];
    float* out = (float*)d_out;

    float* eproj = nullptr;
    float* hlast = nullptr;
    cudaGetSymbolAddress((void**)&eproj, g_eproj);
    cudaGetSymbolAddress((void**)&hlast, g_hlast);

    cudaFuncSetAttribute(gru_scan6,
                         cudaFuncAttributeMaxDynamicSharedMemorySize, SCAN_SM_BYTES);

    dim3 blk(256);
    pack_u<<<256, 128>>>(Uz, Ur, Uh);                                   // launch 0
    sgemm_nt_bias<<<dim3(250, 2), blk>>>(emb, Wz, bz, buz, eproj, 768, 0);    // 1
    sgemm_nt_bias<<<dim3(250, 2), blk>>>(emb, Wr, br, bur, eproj, 768, 256);  // 2
    sgemm_nt_bias<<<dim3(250, 2), blk>>>(emb, Wh, bh, buh, eproj, 768, 512);  // 3
    init_hlast<<<256, 256>>>();                                         // 4 (ncu align)
    gru_scan6<<<128, 256, SCAN_SM_BYTES>>>(x);                          // 5 <- profiled
    sgemm_nt_bias<<<dim3(2, 250), blk>>>(hlast, Wf, bf, nullptr, out, 32000, 0); // 6
}

// round 7
// speedup vs baseline: 3.0750x; 3.0750x over previous
#include <cuda_runtime.h>
#include <cuda_bf16.h>

#define VSZ 32000
#define HSZ 256
#define BSZ 256
#define SSZ 512

typedef unsigned long long ull;

// Scratch (device globals; no allocation allowed)
__device__ float g_eproj[(size_t)VSZ * 768];   // emb @ [Wz;Wr;Wh]^T + biases
__device__ float g_hlast[BSZ * HSZ];
// Transposed packed bf16 U (k-major; coalesced across jg):
//  g_uzr[k][jg] = { bf16x2(Uz cols 2jg,2jg+1 at k), same for Ur }
//  g_uh2[k2][jg] = { bf16x2 Uh cols at k=2k2, bf16x2 Uh cols at k=2k2+1 }
__device__ uint2 g_uzr[256 * 128];
__device__ uint2 g_uh2[128 * 128];

// ---- packed f32x2 helpers (Blackwell sm_103a) ----
__device__ __forceinline__ ull pk2(float lo, float hi) {
    ull r;
    asm("mov.b64 %0, {%1, %2};" : "=l"(r) : "f"(lo), "f"(hi));
    return r;
}
__device__ __forceinline__ void fma2(ull& d, ull a, ull b) {
    asm("fma.rn.f32x2 %0, %1, %2, %0;" : "+l"(d) : "l"(a), "l"(b));
}
__device__ __forceinline__ ull addf2(ull a, ull b) {
    ull r;
    asm("add.rn.f32x2 %0, %1, %2;" : "=l"(r) : "l"(a), "l"(b));
    return r;
}
// butterfly-reduce a f32x2 pair across the 4 kh lane-groups (xor 8, xor 16)
__device__ __forceinline__ ull bflyadd(ull v) {
    v = addf2(v, __shfl_xor_sync(0xffffffffu, v, 8));
    v = addf2(v, __shfl_xor_sync(0xffffffffu, v, 16));
    return v;
}
__device__ __forceinline__ float pick(ull v, int hi_sel) {
    float lo, hi;
    asm("mov.b64 {%0, %1}, %2;" : "=f"(lo), "=f"(hi) : "l"(v));
    return hi_sel ? hi : lo;
}
// bf16x2 (lo16, hi16) -> f32x2 pair, exact
__device__ __forceinline__ ull bf2f2(unsigned v) {
    ull r;
    asm("{\n\t.reg .b32 lo, hi;\n\t"
        "shl.b32 lo, %1, 16;\n\t"
        "and.b32 hi, %1, 0xFFFF0000;\n\t"
        "mov.b64 %0, {lo, hi};\n\t}" : "=l"(r) : "r"(v));
    return r;
}
__device__ __forceinline__ float fast_sigm(float x) {
    float e, r;
    asm("ex2.approx.ftz.f32 %0, %1;" : "=f"(e) : "f"(-1.4426950408889634f * x));
    asm("rcp.approx.ftz.f32 %0, %1;" : "=f"(r) : "f"(1.0f + e));
    return r;
}
__device__ __forceinline__ float fast_tanh(float x) {
    float r;
    asm("tanh.approx.f32 %0, %1;" : "=f"(r) : "f"(x));
    return r;
}
__device__ __forceinline__ unsigned pkbf(float lo, float hi) {
    unsigned short l = __bfloat16_as_ushort(__float2bfloat16(lo));
    unsigned short h = __bfloat16_as_ushort(__float2bfloat16(hi));
    return ((unsigned)h << 16) | (unsigned)l;
}

// ============================================================================
// Pack U into transposed bf16 streams (k-major, coalesced)
// ============================================================================
__global__ void pack_u(const float* __restrict__ Uz, const float* __restrict__ Ur,
                       const float* __restrict__ Uh)
{
    const int k  = blockIdx.x;     // 0..255 (input-k index)
    const int jg = threadIdx.x;    // 0..127 (output col pair)
    const int j0 = 2 * jg;
    unsigned z = pkbf(Uz[j0 * 256 + k], Uz[(j0 + 1) * 256 + k]);
    unsigned r = pkbf(Ur[j0 * 256 + k], Ur[(j0 + 1) * 256 + k]);
    g_uzr[k * 128 + jg] = make_uint2(z, r);
    if (k < 128) {
        const int k2 = k;
        unsigned h0 = pkbf(Uh[j0 * 256 + 2 * k2],     Uh[(j0 + 1) * 256 + 2 * k2]);
        unsigned h1 = pkbf(Uh[j0 * 256 + 2 * k2 + 1], Uh[(j0 + 1) * 256 + 2 * k2 + 1]);
        g_uh2[k2 * 128 + jg] = make_uint2(h0, h1);
    }
}

// ============================================================================
// SGEMM-NT with bias (~90% of scalar f32x2 floor)
// ============================================================================
__global__ void __launch_bounds__(256) sgemm_nt_bias(
    const float* __restrict__ A, const float* __restrict__ Bw,
    const float* __restrict__ bias1, const float* __restrict__ bias2,
    float* __restrict__ C, int ldc, int coloff)
{
    __shared__ __align__(16) float As[16][132];
    __shared__ __align__(16) float Bs[16][132];
    const int t  = threadIdx.x;
    const int tm = t >> 4;
    const int tn = t & 15;

    ull acc[8][4];
#pragma unroll
    for (int i = 0; i < 8; i++)
#pragma unroll
        for (int j = 0; j < 4; j++) acc[i][j] = 0ULL;

    const float* Ab = A  + (size_t)blockIdx.x * 128 * 256;
    const float* Bb = Bw + (size_t)blockIdx.y * 128 * 256;
    const int lr = t >> 2;
    const int lk = (t & 3) << 2;

    for (int k0 = 0; k0 < 256; k0 += 16) {
        float4 a0 = *(const float4*)(Ab + (size_t)lr * 256 + k0 + lk);
        float4 a1 = *(const float4*)(Ab + (size_t)(lr + 64) * 256 + k0 + lk);
        float4 b0 = *(const float4*)(Bb + (size_t)lr * 256 + k0 + lk);
        float4 b1 = *(const float4*)(Bb + (size_t)(lr + 64) * 256 + k0 + lk);
        __syncthreads();
        As[lk + 0][lr] = a0.x; As[lk + 1][lr] = a0.y;
        As[lk + 2][lr] = a0.z; As[lk + 3][lr] = a0.w;
        As[lk + 0][lr + 64] = a1.x; As[lk + 1][lr + 64] = a1.y;
        As[lk + 2][lr + 64] = a1.z; As[lk + 3][lr + 64] = a1.w;
        Bs[lk + 0][lr] = b0.x; Bs[lk + 1][lr] = b0.y;
        Bs[lk + 2][lr] = b0.z; Bs[lk + 3][lr] = b0.w;
        Bs[lk + 0][lr + 64] = b1.x; Bs[lk + 1][lr + 64] = b1.y;
        Bs[lk + 2][lr + 64] = b1.z; Bs[lk + 3][lr + 64] = b1.w;
        __syncthreads();
#pragma unroll
        for (int kk = 0; kk < 16; kk++) {
            float4 av0 = *(const float4*)(&As[kk][tm * 8]);
            float4 av1 = *(const float4*)(&As[kk][tm * 8 + 4]);
            const ull* bp = (const ull*)(&Bs[kk][tn * 8]);
            ull b2_0 = bp[0], b2_1 = bp[1], b2_2 = bp[2], b2_3 = bp[3];
            float av[8] = {av0.x, av0.y, av0.z, av0.w, av1.x, av1.y, av1.z, av1.w};
#pragma unroll
            for (int i = 0; i < 8; i++) {
                ull a2 = pk2(av[i], av[i]);
                fma2(acc[i][0], a2, b2_0);
                fma2(acc[i][1], a2, b2_1);
                fma2(acc[i][2], a2, b2_2);
                fma2(acc[i][3], a2, b2_3);
            }
        }
    }

    const int row0 = blockIdx.x * 128 + tm * 8;
    const int col0 = blockIdx.y * 128 + tn * 8;
#pragma unroll
    for (int i = 0; i < 8; i++) {
#pragma unroll
        for (int j = 0; j < 4; j++) {
            float lo, hi;
            asm("mov.b64 {%0, %1}, %2;" : "=f"(lo), "=f"(hi) : "l"(acc[i][j]));
            int n0 = col0 + j * 2;
            float e0 = bias1[n0]     + (bias2 ? bias2[n0]     : 0.0f);
            float e1 = bias1[n0 + 1] + (bias2 ? bias2[n0 + 1] : 0.0f);
            C[(size_t)(row0 + i) * ldc + coloff + n0]     = lo + e0;
            C[(size_t)(row0 + i) * ldc + coloff + n0 + 1] = hi + e1;
        }
    }
}

// ============================================================================
// GRU scan v7: 128 CTAs x 2 batch rows x 512 threads.
// Warp-contained k-split: lane = (jp&7 | kh<<3); partials for a col-pair sit
// in lanes {j, j+8, j+16, j+24} -> butterfly-shuffle reduction (xor8, xor16).
// No red smem, 2 barriers/step. After reduction each lane owns one
// (row = kh&1, col = 2jp + (kh>>1)) unit: activations, h scalar, state STS.
// k<128 of both streams pinned in SMEM; k>=128 via depth-16/8 register rings
// with cross-step wraparound.
// ============================================================================
#define SCAN_SM_BYTES 204800   // 128K pin_zr + 64K pin_uh + 4K hdup + 4K srhdup

__global__ void __launch_bounds__(512, 1) gru_scan7(const int* __restrict__ x)
{
    extern __shared__ __align__(16) char smraw[];
    uint2* pin_zr = (uint2*)smraw;                    // [k<128][jg] 131072 B
    uint2* pin_uh = (uint2*)(smraw + 131072);         // [k2<64][jg]  65536 B
    ull*   hdup   = (ull*)(smraw + 196608);           // [col][row] pk2(h,h)
    ull*   srhdup = (ull*)(smraw + 200704);           // [col][row] pk2(rh,rh)

    const int t    = threadIdx.x;
    const int lane = t & 31;
    const int w    = t >> 5;
    const int jp   = (w << 3) | (lane & 7);   // col-pair 0..127
    const int kh   = lane >> 3;               // 0..3
    const int kb   = kh << 6;                 // k base (64 per kh)
    const int row  = kh & 1;                  // batch row within CTA
    const int csel = kh >> 1;                 // which col of the pair
    const int mycol = (jp << 1) | csel;
    const int b0   = blockIdx.x * 2;

    // ---- pin k<128 of both streams + zero state ----
    for (int i = t; i < 16384; i += 512) pin_zr[i] = g_uzr[i];
    for (int i = t; i < 8192; i += 512)  pin_uh[i] = g_uh2[i];
    hdup[t] = 0ULL; srhdup[t] = 0ULL;
    __syncthreads();

    // per-lane stream base (smem for kh<2, global for kh>=2; generic LD)
    const uint2* zsrc  = ((kh < 2) ? pin_zr : g_uzr) + kb * 128 + jp;
    const uint2* h2src = ((kh < 2) ? pin_uh : g_uh2) + (kh * 32) * 128 + jp;

    // rolling register rings (persist across steps; cross-step wraparound)
    uint2 zr_r[16], uh_r[8];
#pragma unroll
    for (int i = 0; i < 16; i++) zr_r[i] = zsrc[i * 128];
#pragma unroll
    for (int i = 0; i < 8; i++)  uh_r[i] = h2src[i * 128];

    // lane-owned state + e/token pipeline
    float hold = 0.0f, zg = 0.0f;
    const int xrow = (b0 + row) * SSZ;
    int tok = __ldg(&x[xrow]);
    const float* e0 = g_eproj + (size_t)tok * 768;
    float ez = __ldg(e0 + mycol);
    float er = __ldg(e0 + 256 + mycol);
    float eh = __ldg(e0 + 512 + mycol);
    int tok1 = __ldg(&x[xrow + 1]);

    for (int s = 0; s < SSZ; s++) {
        // ================= phase 1: z, r partials over 64 k =================
        ull az0 = 0, az1 = 0, ar0 = 0, ar1 = 0;
#pragma unroll
        for (int kk = 0; kk < 64; kk++) {
            uint2 u = zr_r[kk & 15];
            zr_r[kk & 15] = zsrc[((kk + 16) & 63) * 128];
            ull uz2 = bf2f2(u.x);
            ull ur2 = bf2f2(u.y);
            ulonglong2 hp = *(const ulonglong2*)(hdup + ((kb + kk) << 1));
            fma2(az0, uz2, hp.x); fma2(az1, uz2, hp.y);
            fma2(ar0, ur2, hp.x); fma2(ar1, ur2, hp.y);
        }
        // warp butterfly reduction across kh groups
        az0 = bflyadd(az0); az1 = bflyadd(az1);
        ar0 = bflyadd(ar0); ar1 = bflyadd(ar1);

        const float sz = pick(row ? az1 : az0, csel);
        const float sr = pick(row ? ar1 : ar0, csel);
        zg = fast_sigm(sz + ez);
        const float rg = fast_sigm(sr + er);
        const float rh = rg * hold;
        srhdup[(mycol << 1) | row] = pk2(rh, rh);
        // prefetch next step's z/r e-values
        const float* en = g_eproj + (size_t)tok1 * 768;
        ez = __ldg(en + mycol);
        er = __ldg(en + 256 + mycol);
        __syncthreads();

        // ================= phase 2: h_tilde partials over 64 k =================
        ull ah0 = 0, ah1 = 0;
#pragma unroll
        for (int kk = 0; kk < 32; kk++) {
            uint2 u = uh_r[kk & 7];
            uh_r[kk & 7] = h2src[((kk + 8) & 31) * 128];
            ull uh0 = bf2f2(u.x);
            ull uh1 = bf2f2(u.y);
            const int k0 = kb + (kk << 1);
            ulonglong2 s0 = *(const ulonglong2*)(srhdup + (k0 << 1));
            ulonglong2 s1 = *(const ulonglong2*)(srhdup + (k0 << 1) + 2);
            fma2(ah0, uh0, s0.x); fma2(ah1, uh0, s0.y);
            fma2(ah0, uh1, s1.x); fma2(ah1, uh1, s1.y);
        }
        ah0 = bflyadd(ah0); ah1 = bflyadd(ah1);

        const float sh = pick(row ? ah1 : ah0, csel);
        const float ht = fast_tanh(sh + eh);
        hold += zg * (ht - hold);
        hdup[(mycol << 1) | row] = pk2(hold, hold);
        // prefetch next step's h e-value; advance token pipeline to s+2
        eh = __ldg(en + 512 + mycol);
        {
            int s2 = (s + 2 < SSZ) ? s + 2 : SSZ - 1;
            tok1 = __ldg(&x[xrow + s2]);
        }
        __syncthreads();
    }

    g_hlast[(size_t)(b0 + row) * HSZ + mycol] = hold;
}

// ============================================================================
extern "C" void kernel_launch(void* const* d_in, const int* in_sizes, int n_in,
                              void* d_out, int out_size)
{
    const int*   x   = (const int*)  d_in[0];
    const float* emb = (const float*)d_in[1];
    const float* Wz  = (const float*)d_in[2];
    const float* bz  = (const float*)d_in[3];
    const float* Uz  = (const float*)d_in[4];
    const float* buz = (const float*)d_in[5];
    const float* Wr  = (const float*)d_in[6];
    const float* br  = (const float*)d_in[7];
    const float* Ur  = (const float*)d_in[8];
    const float* bur = (const float*)d_in[9];
    const float* Wh  = (const float*)d_in[10];
    const float* bh  = (const float*)d_in[11];
    const float* Uh  = (const float*)d_in[12];
    const float* buh = (const float*)d_in[13];
    const float* Wf  = (const float*)d_in[14];
    const float* bf  = (const float*)d_in[15];
    float* out = (float*)d_out;

    float* eproj = nullptr;
    float* hlast = nullptr;
    cudaGetSymbolAddress((void**)&eproj, g_eproj);
    cudaGetSymbolAddress((void**)&hlast, g_hlast);

    cudaFuncSetAttribute(gru_scan7,
                         cudaFuncAttributeMaxDynamicSharedMemorySize, SCAN_SM_BYTES);

    dim3 blk(256);
    pack_u<<<256, 128>>>(Uz, Ur, Uh);
    sgemm_nt_bias<<<dim3(250, 2), blk>>>(emb, Wz, bz, buz, eproj, 768, 0);
    sgemm_nt_bias<<<dim3(250, 2), blk>>>(emb, Wr, br, bur, eproj, 768, 256);
    sgemm_nt_bias<<<dim3(250, 2), blk>>>(emb, Wh, bh, buh, eproj, 768, 512);

    gru_scan7<<<128, 512, SCAN_SM_BYTES>>>(x);

    sgemm_nt_bias<<<dim3(2, 250), blk>>>(hlast, Wf, bf, nullptr, out, 32000, 0);
}

// round 8
// speedup vs baseline: 5.0680x; 1.6481x over previous
#include <cuda_runtime.h>
#include <cuda_bf16.h>

#define VSZ 32000
#define HSZ 256
#define BSZ 256
#define SSZ 512

typedef unsigned long long ull;

// Scratch (device globals; no allocation allowed)
__device__ float g_eproj[(size_t)VSZ * 768];   // emb @ [Wz;Wr;Wh]^T + biases
__device__ float g_hlast[BSZ * HSZ];
// Transposed packed bf16 U, k-grouped for uint4 loads:
//  g_zr4[k2][jg] = { z(2k2), r(2k2), z(2k2+1), r(2k2+1) }  (each = bf16x2 of cols 2jg,2jg+1)
//  g_uh4[k4][jg] = { h(4k4), h(4k4+1), h(4k4+2), h(4k4+3) }
__device__ uint4 g_zr4[128 * 128];
__device__ uint4 g_uh4[64 * 128];

// ---- packed f32x2 helpers (Blackwell sm_103a) ----
__device__ __forceinline__ ull pk2(float lo, float hi) {
    ull r;
    asm("mov.b64 %0, {%1, %2};" : "=l"(r) : "f"(lo), "f"(hi));
    return r;
}
__device__ __forceinline__ void fma2(ull& d, ull a, ull b) {
    asm("fma.rn.f32x2 %0, %1, %2, %0;" : "+l"(d) : "l"(a), "l"(b));
}
__device__ __forceinline__ ull addf2(ull a, ull b) {
    ull r;
    asm("add.rn.f32x2 %0, %1, %2;" : "=l"(r) : "l"(a), "l"(b));
    return r;
}
__device__ __forceinline__ ull bflyadd(ull v) {
    v = addf2(v, __shfl_xor_sync(0xffffffffu, v, 8));
    v = addf2(v, __shfl_xor_sync(0xffffffffu, v, 16));
    return v;
}
__device__ __forceinline__ float pick(ull v, int hi_sel) {
    float lo, hi;
    asm("mov.b64 {%0, %1}, %2;" : "=f"(lo), "=f"(hi) : "l"(v));
    return hi_sel ? hi : lo;
}
__device__ __forceinline__ ull bf2f2(unsigned v) {
    ull r;
    asm("{\n\t.reg .b32 lo, hi;\n\t"
        "shl.b32 lo, %1, 16;\n\t"
        "and.b32 hi, %1, 0xFFFF0000;\n\t"
        "mov.b64 %0, {lo, hi};\n\t}" : "=l"(r) : "r"(v));
    return r;
}
__device__ __forceinline__ float fast_sigm(float x) {
    float e, r;
    asm("ex2.approx.ftz.f32 %0, %1;" : "=f"(e) : "f"(-1.4426950408889634f * x));
    asm("rcp.approx.ftz.f32 %0, %1;" : "=f"(r) : "f"(1.0f + e));
    return r;
}
__device__ __forceinline__ float fast_tanh(float x) {
    float r;
    asm("tanh.approx.f32 %0, %1;" : "=f"(r) : "f"(x));
    return r;
}
__device__ __forceinline__ unsigned pkbf(float lo, float hi) {
    unsigned short l = __bfloat16_as_ushort(__float2bfloat16(lo));
    unsigned short h = __bfloat16_as_ushort(__float2bfloat16(hi));
    return ((unsigned)h << 16) | (unsigned)l;
}

// ============================================================================
// Pack U into transposed bf16 uint4 streams
// ============================================================================
__global__ void pack_u(const float* __restrict__ Uz, const float* __restrict__ Ur,
                       const float* __restrict__ Uh)
{
    const int k2 = blockIdx.x;     // 0..127
    const int jg = threadIdx.x;    // 0..127
    const int j0 = 2 * jg;
    const int ka = 2 * k2, kb = 2 * k2 + 1;
    uint4 v;
    v.x = pkbf(Uz[j0 * 256 + ka], Uz[(j0 + 1) * 256 + ka]);
    v.y = pkbf(Ur[j0 * 256 + ka], Ur[(j0 + 1) * 256 + ka]);
    v.z = pkbf(Uz[j0 * 256 + kb], Uz[(j0 + 1) * 256 + kb]);
    v.w = pkbf(Ur[j0 * 256 + kb], Ur[(j0 + 1) * 256 + kb]);
    g_zr4[k2 * 128 + jg] = v;
    if (k2 < 64) {
        const int kc = 4 * k2;
        uint4 h;
        h.x = pkbf(Uh[j0 * 256 + kc],     Uh[(j0 + 1) * 256 + kc]);
        h.y = pkbf(Uh[j0 * 256 + kc + 1], Uh[(j0 + 1) * 256 + kc + 1]);
        h.z = pkbf(Uh[j0 * 256 + kc + 2], Uh[(j0 + 1) * 256 + kc + 2]);
        h.w = pkbf(Uh[j0 * 256 + kc + 3], Uh[(j0 + 1) * 256 + kc + 3]);
        g_uh4[k2 * 128 + jg] = h;
    }
}

// ============================================================================
// SGEMM-NT with bias (~90% of scalar f32x2 floor)
// ============================================================================
__global__ void __launch_bounds__(256) sgemm_nt_bias(
    const float* __restrict__ A, const float* __restrict__ Bw,
    const float* __restrict__ bias1, const float* __restrict__ bias2,
    float* __restrict__ C, int ldc, int coloff)
{
    __shared__ __align__(16) float As[16][132];
    __shared__ __align__(16) float Bs[16][132];
    const int t  = threadIdx.x;
    const int tm = t >> 4;
    const int tn = t & 15;

    ull acc[8][4];
#pragma unroll
    for (int i = 0; i < 8; i++)
#pragma unroll
        for (int j = 0; j < 4; j++) acc[i][j] = 0ULL;

    const float* Ab = A  + (size_t)blockIdx.x * 128 * 256;
    const float* Bb = Bw + (size_t)blockIdx.y * 128 * 256;
    const int lr = t >> 2;
    const int lk = (t & 3) << 2;

    for (int k0 = 0; k0 < 256; k0 += 16) {
        float4 a0 = *(const float4*)(Ab + (size_t)lr * 256 + k0 + lk);
        float4 a1 = *(const float4*)(Ab + (size_t)(lr + 64) * 256 + k0 + lk);
        float4 b0 = *(const float4*)(Bb + (size_t)lr * 256 + k0 + lk);
        float4 b1 = *(const float4*)(Bb + (size_t)(lr + 64) * 256 + k0 + lk);
        __syncthreads();
        As[lk + 0][lr] = a0.x; As[lk + 1][lr] = a0.y;
        As[lk + 2][lr] = a0.z; As[lk + 3][lr] = a0.w;
        As[lk + 0][lr + 64] = a1.x; As[lk + 1][lr + 64] = a1.y;
        As[lk + 2][lr + 64] = a1.z; As[lk + 3][lr + 64] = a1.w;
        Bs[lk + 0][lr] = b0.x; Bs[lk + 1][lr] = b0.y;
        Bs[lk + 2][lr] = b0.z; Bs[lk + 3][lr] = b0.w;
        Bs[lk + 0][lr + 64] = b1.x; Bs[lk + 1][lr + 64] = b1.y;
        Bs[lk + 2][lr + 64] = b1.z; Bs[lk + 3][lr + 64] = b1.w;
        __syncthreads();
#pragma unroll
        for (int kk = 0; kk < 16; kk++) {
            float4 av0 = *(const float4*)(&As[kk][tm * 8]);
            float4 av1 = *(const float4*)(&As[kk][tm * 8 + 4]);
            const ull* bp = (const ull*)(&Bs[kk][tn * 8]);
            ull b2_0 = bp[0], b2_1 = bp[1], b2_2 = bp[2], b2_3 = bp[3];
            float av[8] = {av0.x, av0.y, av0.z, av0.w, av1.x, av1.y, av1.z, av1.w};
#pragma unroll
            for (int i = 0; i < 8; i++) {
                ull a2 = pk2(av[i], av[i]);
                fma2(acc[i][0], a2, b2_0);
                fma2(acc[i][1], a2, b2_1);
                fma2(acc[i][2], a2, b2_2);
                fma2(acc[i][3], a2, b2_3);
            }
        }
    }

    const int row0 = blockIdx.x * 128 + tm * 8;
    const int col0 = blockIdx.y * 128 + tn * 8;
#pragma unroll
    for (int i = 0; i < 8; i++) {
#pragma unroll
        for (int j = 0; j < 4; j++) {
            float lo, hi;
            asm("mov.b64 {%0, %1}, %2;" : "=f"(lo), "=f"(hi) : "l"(acc[i][j]));
            int n0 = col0 + j * 2;
            float e0 = bias1[n0]     + (bias2 ? bias2[n0]     : 0.0f);
            float e1 = bias1[n0 + 1] + (bias2 ? bias2[n0 + 1] : 0.0f);
            C[(size_t)(row0 + i) * ldc + coloff + n0]     = lo + e0;
            C[(size_t)(row0 + i) * ldc + coloff + n0 + 1] = hi + e1;
        }
    }
}

// ============================================================================
// GRU scan v8: 128 CTAs x 2 batch rows x 512 threads.
// Warp-contained k-split butterfly (as v7), but U pinned BY COLUMN (jg<64):
// address space is uniform per warp -> explicit LDS-only / LDG-only loop
// bodies. uint4 U loads; hdup/srhdup padded +2 ull per 64-k block so the
// 4 kh-group broadcast LDS.128 reads are bank-conflict-free.
// ============================================================================
#define SCAN_SM_BYTES 204928

// phase-1 fma body for one uint4 (2 k-pairs) at k-pair index kk within chunk
#define P1BODY(u, hb, kk)                                                   \
    {                                                                       \
        ull uz0 = bf2f2((u).x), ur0 = bf2f2((u).y);                         \
        ull uz1 = bf2f2((u).z), ur1 = bf2f2((u).w);                         \
        ulonglong2 h0 = *(const ulonglong2*)(hdup + (hb) + 4 * (kk));       \
        ulonglong2 h1 = *(const ulonglong2*)(hdup + (hb) + 4 * (kk) + 2);   \
        fma2(az0, uz0, h0.x); fma2(az1, uz0, h0.y);                         \
        fma2(ar0, ur0, h0.x); fma2(ar1, ur0, h0.y);                         \
        fma2(az0, uz1, h1.x); fma2(az1, uz1, h1.y);                         \
        fma2(ar0, ur1, h1.x); fma2(ar1, ur1, h1.y);                         \
    }

// phase-2 fma body for one uint4 (4 k) at k4 index kk within chunk
#define P2BODY(u, sb, kk)                                                   \
    {                                                                       \
        ull uh0 = bf2f2((u).x), uh1 = bf2f2((u).y);                         \
        ull uh2 = bf2f2((u).z), uh3 = bf2f2((u).w);                         \
        ulonglong2 s0 = *(const ulonglong2*)(srhdup + (sb) + 8 * (kk));     \
        ulonglong2 s1 = *(const ulonglong2*)(srhdup + (sb) + 8 * (kk) + 2); \
        ulonglong2 s2 = *(const ulonglong2*)(srhdup + (sb) + 8 * (kk) + 4); \
        ulonglong2 s3 = *(const ulonglong2*)(srhdup + (sb) + 8 * (kk) + 6); \
        fma2(ah0, uh0, s0.x); fma2(ah1, uh0, s0.y);                         \
        fma2(ah0, uh1, s1.x); fma2(ah1, uh1, s1.y);                         \
        fma2(ah0, uh2, s2.x); fma2(ah1, uh2, s2.y);                         \
        fma2(ah0, uh3, s3.x); fma2(ah1, uh3, s3.y);                         \
    }

__global__ void __launch_bounds__(512, 1) gru_scan8(const int* __restrict__ x)
{
    extern __shared__ __align__(16) char smraw[];
    uint4* pin_zr4 = (uint4*)smraw;                   // [k2<128][jg<64] 131072 B
    uint4* pin_uh4 = (uint4*)(smraw + 131072);        // [k4<64][jg<64]   65536 B
    ull*   hdup    = (ull*)(smraw + 196608);          // 520 ull, padded
    ull*   srhdup  = (ull*)(smraw + 200768);          // 520 ull, padded

    const int t    = threadIdx.x;
    const int lane = t & 31;
    const int w    = t >> 5;
    const int jp   = (w << 3) | (lane & 7);   // col-pair 0..127
    const int kh   = lane >> 3;               // 0..3
    const int row  = kh & 1;
    const int csel = kh >> 1;
    const int mycol = (jp << 1) | csel;
    const int b0   = blockIdx.x * 2;
    const bool smw = (w < 8);                 // uniform per warp

    // ---- pin columns jg<64 + zero padded state ----
    for (int i = t; i < 128 * 64; i += 512)
        pin_zr4[i] = g_zr4[(i >> 6) * 128 + (i & 63)];
    for (int i = t; i < 64 * 64; i += 512)
        pin_uh4[i] = g_uh4[(i >> 6) * 128 + (i & 63)];
    for (int i = t; i < 520; i += 512) { hdup[i] = 0ULL; srhdup[i] = 0ULL; }
    __syncthreads();

    // per-warp-uniform stream bases (k2 base = kh*32; k4 base = kh*16)
    const uint4* zsP = pin_zr4 + (kh * 32) * 64 + jp;        // smem, stride 64
    const uint4* zgP = g_zr4   + (kh * 32) * 128 + jp;       // gmem, stride 128
    const uint4* hsP = pin_uh4 + (kh * 16) * 64 + jp;
    const uint4* hgP = g_uh4   + (kh * 16) * 128 + jp;
    const int hb = 130 * kh;   // padded ull base for this kh's 64-k block

    // global register rings (only live for global warps)
    uint4 zr_ring[8], uh_ring[4];
    if (!smw) {
#pragma unroll
        for (int i = 0; i < 8; i++) zr_ring[i] = zgP[i * 128];
#pragma unroll
        for (int i = 0; i < 4; i++) uh_ring[i] = hgP[i * 128];
    }

    // lane-owned state + e/token pipeline
    float hold = 0.0f, zg = 0.0f;
    const int xrow = (b0 + row) * SSZ;
    const int wc = 2 * mycol + row + ((mycol >> 6) << 1);   // padded state idx
    int tok = __ldg(&x[xrow]);
    const float* e0 = g_eproj + (size_t)tok * 768;
    float ez = __ldg(e0 + mycol);
    float er = __ldg(e0 + 256 + mycol);
    float eh = __ldg(e0 + 512 + mycol);
    int tok1 = __ldg(&x[xrow + 1]);

    for (int s = 0; s < SSZ; s++) {
        // ================= phase 1: z, r partials (64 k) =================
        ull az0 = 0, az1 = 0, ar0 = 0, ar1 = 0;
        if (smw) {
#pragma unroll
            for (int kk = 0; kk < 32; kk++) {
                uint4 u = zsP[kk * 64];
                P1BODY(u, hb, kk);
            }
        } else {
#pragma unroll
            for (int kk = 0; kk < 32; kk++) {
                uint4 u = zr_ring[kk & 7];
                zr_ring[kk & 7] = zgP[((kk + 8) & 31) * 128];
                P1BODY(u, hb, kk);
            }
        }
        az0 = bflyadd(az0); az1 = bflyadd(az1);
        ar0 = bflyadd(ar0); ar1 = bflyadd(ar1);

        const float sz = pick(row ? az1 : az0, csel);
        const float sr = pick(row ? ar1 : ar0, csel);
        zg = fast_sigm(sz + ez);
        const float rg = fast_sigm(sr + er);
        const float rh = rg * hold;
        srhdup[wc] = pk2(rh, rh);
        const float* en = g_eproj + (size_t)tok1 * 768;
        ez = __ldg(en + mycol);
        er = __ldg(en + 256 + mycol);
        __syncthreads();

        // ================= phase 2: h_tilde partials (64 k) =================
        ull ah0 = 0, ah1 = 0;
        if (smw) {
#pragma unroll
            for (int kk = 0; kk < 16; kk++) {
                uint4 u = hsP[kk * 64];
                P2BODY(u, hb, kk);
            }
        } else {
#pragma unroll
            for (int kk = 0; kk < 16; kk++) {
                uint4 u = uh_ring[kk & 3];
                uh_ring[kk & 3] = hgP[((kk + 4) & 15) * 128];
                P2BODY(u, hb, kk);
            }
        }
        ah0 = bflyadd(ah0); ah1 = bflyadd(ah1);

        const float sh = pick(row ? ah1 : ah0, csel);
        const float ht = fast_tanh(sh + eh);
        hold += zg * (ht - hold);
        hdup[wc] = pk2(hold, hold);
        eh = __ldg(en + 512 + mycol);
        {
            int s2 = (s + 2 < SSZ) ? s + 2 : SSZ - 1;
            tok1 = __ldg(&x[xrow + s2]);
        }
        __syncthreads();
    }

    g_hlast[(size_t)(b0 + row) * HSZ + mycol] = hold;
}

// ============================================================================
extern "C" void kernel_launch(void* const* d_in, const int* in_sizes, int n_in,
                              void* d_out, int out_size)
{
    const int*   x   = (const int*)  d_in[0];
    const float* emb = (const float*)d_in[1];
    const float* Wz  = (const float*)d_in[2];
    const float* bz  = (const float*)d_in[3];
    const float* Uz  = (const float*)d_in[4];
    const float* buz = (const float*)d_in[5];
    const float* Wr  = (const float*)d_in[6];
    const float* br  = (const float*)d_in[7];
    const float* Ur  = (const float*)d_in[8];
    const float* bur = (const float*)d_in[9];
    const float* Wh  = (const float*)d_in[10];
    const float* bh  = (const float*)d_in[11];
    const float* Uh  = (const float*)d_in[12];
    const float* buh = (const float*)d_in[13];
    const float* Wf  = (const float*)d_in[14];
    const float* bf  = (const float*)d_in[15];
    float* out = (float*)d_out;

    float* eproj = nullptr;
    float* hlast = nullptr;
    cudaGetSymbolAddress((void**)&eproj, g_eproj);
    cudaGetSymbolAddress((void**)&hlast, g_hlast);

    cudaFuncSetAttribute(gru_scan8,
                         cudaFuncAttributeMaxDynamicSharedMemorySize, SCAN_SM_BYTES);

    dim3 blk(256);
    pack_u<<<128, 128>>>(Uz, Ur, Uh);
    sgemm_nt_bias<<<dim3(250, 2), blk>>>(emb, Wz, bz, buz, eproj, 768, 0);
    sgemm_nt_bias<<<dim3(250, 2), blk>>>(emb, Wr, br, bur, eproj, 768, 256);
    sgemm_nt_bias<<<dim3(250, 2), blk>>>(emb, Wh, bh, buh, eproj, 768, 512);

    gru_scan8<<<128, 512, SCAN_SM_BYTES>>>(x);

    sgemm_nt_bias<<<dim3(2, 250), blk>>>(hlast, Wf, bf, nullptr, out, 32000, 0);
}